// round 12
// baseline (speedup 1.0000x reference)
#include <cuda_runtime.h>
#include <cuda_bf16.h>
#include <cuda_fp8.h>
#include <math.h>
#include <stdint.h>

// ---------------------------------------------------------------- shapes
constexpr int Bn = 16, Tn = 512, Hn = 512, Vn = 4096, Ln = 64, Jn = 66;
constexpr int Mn = Bn * Tn;
constexpr int Smax = 2 * Ln + 1;
constexpr float NEGF = -1e30f;
constexpr float LOG2E = 1.4426950408889634f;
constexpr float LN2 = 0.6931471805599453f;
constexpr float WSCALE = 16.0f;
constexpr float INV_WSCALE = 1.0f / 16.0f;

// ---------------------------------------------------------------- scratch
__device__ uint8_t g_A8[(size_t)Mn * Hn];
__device__ uint8_t g_B8[(size_t)Vn * Hn];
__device__ float2  g_part[(size_t)Mn * 128];
__device__ float   g_gath[(size_t)Mn * Jn];
__device__ float   g_emit[(size_t)Mn * Jn];
__device__ int     g_rep[Bn * Jn];
__device__ float   g_ll[Bn];
__device__ int     g_ctr;
__device__ int     g_rowctr[64];

// ---------------------------------------------------------------- helpers
__device__ __forceinline__ uint32_t smem_u32(const void* p) {
    uint32_t a;
    asm("{ .reg .u64 t; cvta.to.shared.u64 t, %1; cvt.u32.u64 %0, t; }" : "=r"(a) : "l"(p));
    return a;
}
__device__ __forceinline__ void ldm_x4(uint32_t* r, uint32_t addr) {
    asm volatile("ldmatrix.sync.aligned.m8n8.x4.shared.b16 {%0,%1,%2,%3}, [%4];"
                 : "=r"(r[0]), "=r"(r[1]), "=r"(r[2]), "=r"(r[3]) : "r"(addr));
}
__device__ __forceinline__ void ldm_x2(uint32_t* r, uint32_t addr) {
    asm volatile("ldmatrix.sync.aligned.m8n8.x2.shared.b16 {%0,%1}, [%2];"
                 : "=r"(r[0]), "=r"(r[1]) : "r"(addr));
}
__device__ __forceinline__ void mma_fp8(float* d, const uint32_t* a, const uint32_t* b) {
    asm volatile("mma.sync.aligned.m16n8k32.row.col.f32.e4m3.e4m3.f32 "
                 "{%0,%1,%2,%3}, {%4,%5,%6,%7}, {%8,%9}, {%0,%1,%2,%3};"
                 : "+f"(d[0]), "+f"(d[1]), "+f"(d[2]), "+f"(d[3])
                 : "r"(a[0]), "r"(a[1]), "r"(a[2]), "r"(a[3]), "r"(b[0]), "r"(b[1]));
}
__device__ __forceinline__ float ex2(float x) {
    float r; asm("ex2.approx.ftz.f32 %0, %1;" : "=f"(r) : "f"(x)); return r;
}
__device__ __forceinline__ float lg2(float x) {
    float r; asm("lg2.approx.f32 %0, %1;" : "=f"(r) : "f"(x)); return r;
}
__device__ __forceinline__ float lse2(float x, float y) {
    float m = fmaxf(x, y);
    return m + lg2(ex2(x - m) + ex2(y - m));
}
__device__ __forceinline__ float lse3(float x, float y, float z) {
    float m = fmaxf(fmaxf(x, y), z);
    return m + lg2(ex2(x - m) + ex2(y - m) + ex2(z - m));
}
__device__ __forceinline__ uint16_t f2_to_e4m3x2(float x, float y) {
    return (uint16_t)__nv_cvt_float2_to_fp8x2(make_float2(x, y), __NV_SATFINITE, __NV_E4M3);
}
#define CP_ASYNC16(dst, src) \
    asm volatile("cp.async.cg.shared.global [%0], [%1], 16;" :: "r"(dst), "l"(src) : "memory")
#define CP_COMMIT() asm volatile("cp.async.commit_group;" ::: "memory")
#define CP_WAIT2()  asm volatile("cp.async.wait_group 2;" ::: "memory")

// ---------------------------------------------------------------- fused preprocessing
__global__ __launch_bounds__(256) void prep_kernel(const float* __restrict__ hs,
                                                   const float* __restrict__ W,
                                                   const int* __restrict__ ys) {
    const int bid = blockIdx.x, tid = threadIdx.x;
    if (bid < 4096) {
        size_t i = (size_t)bid * 256 + tid;
        float4 v = ((const float4*)hs)[i];
        uint32_t u = (uint32_t)f2_to_e4m3x2(v.x, v.y) | ((uint32_t)f2_to_e4m3x2(v.z, v.w) << 16);
        ((uint32_t*)g_A8)[i] = u;
    } else if (bid < 6144) {
        __shared__ float tile[32][33];
        const int vb = bid - 4096;
        const int v0 = (vb & 127) * 32, k0 = (vb >> 7) * 32;
        const int tx = tid & 31, ty = tid >> 5;
#pragma unroll
        for (int j = 0; j < 4; j++)
            tile[ty + 8 * j][tx] = W[(size_t)(k0 + ty + 8 * j) * Vn + v0 + tx];
        __syncthreads();
#pragma unroll
        for (int j = 0; j < 4; j++) {
            int vl = ty + 8 * j;
            __nv_fp8_e4m3 q(tile[tx][vl] * WSCALE);
            g_B8[(size_t)(v0 + vl) * Hn + k0 + tx] = *(uint8_t*)&q;
        }
    } else if (bid < 6160) {
        const int b = bid - 6144;
        const int j = tid;
        if (j < 65) {
            const int vid = (j == 0) ? 0 : ys[b * Ln + j - 1];
            int r = j;
            for (int q = 0; q < j; q++) {
                const int vq = (q == 0) ? 0 : ys[b * Ln + q - 1];
                if (vq == vid) { r = q; break; }
            }
            g_rep[b * Jn + j] = r;
        }
    } else {
        if (tid == 0) g_ctr = 0;
        if (tid < 64) g_rowctr[tid] = 0;
    }
}

// ---------------------------------------------------------------- FP8 MMA GEMM + inline LSE/emit
constexpr int STAGES = 4;
constexpr int STAGE_BYTES = 16384;
constexpr int GEMM_SMEM = STAGES * STAGE_BYTES;

__global__ __launch_bounds__(256, 2) void gemm_mma_kernel(const int* __restrict__ ys,
                                                          const float* __restrict__ bias) {
    extern __shared__ __align__(1024) char sm[];
    __shared__ float sbias[128];
    __shared__ int stable[128];
    __shared__ int slast;

    const int tid = threadIdx.x, w = tid >> 5, lane = tid & 31;
    const int bn = blockIdx.x * 128, bm = blockIdx.y * 128;
    const int b = blockIdx.y >> 2;

    if (tid < 128) { sbias[tid] = bias[bn + tid]; stable[tid] = -1; }
    __syncthreads();
    if (tid == 0) {
        for (int j = 0; j < 65; j++) {
            const int vid = (j == 0) ? 0 : ys[b * Ln + j - 1];
            const int idx = vid - bn;
            if (idx >= 0 && idx < 128 && stable[idx] < 0) stable[idx] = j;
        }
    }

    const int row = tid >> 1, kp = tid & 1;
    const uint8_t* gA = g_A8 + (size_t)(bm + row) * Hn + kp * 16;
    const uint8_t* gB = g_B8 + (size_t)(bn + row) * Hn + kp * 16;
    const uint32_t smb = smem_u32(sm);
    const uint32_t stsA = smb + (uint32_t)(kp * 2) * 2048 + (uint32_t)row * 16;

    const int wm = w >> 2, wn = w & 3;
    const uint32_t aBase = smb + (uint32_t)(wm * 64 + (lane & 15)) * 16 + (uint32_t)(lane >> 4) * 2048;
    const uint32_t bBase = smb + 8192 + (uint32_t)(wn * 32 + (lane & 7)) * 16 + (uint32_t)((lane >> 3) & 1) * 2048;

    float acc[4][4][4];
#pragma unroll
    for (int mi = 0; mi < 4; mi++)
#pragma unroll
        for (int ni = 0; ni < 4; ni++)
#pragma unroll
            for (int e = 0; e < 4; e++) acc[mi][ni][e] = 0.f;

    const int NC = Hn / 64;

#define ISSUE_STAGE(slot, c)                                                   \
    do {                                                                       \
        const uint32_t so = (uint32_t)(slot) * STAGE_BYTES;                    \
        _Pragma("unroll")                                                      \
        for (int i = 0; i < 2; i++) {                                          \
            CP_ASYNC16(stsA + so + i * 2048, gA + (c) * 64 + i * 32);          \
            CP_ASYNC16(stsA + so + 8192 + i * 2048, gB + (c) * 64 + i * 32);   \
        }                                                                      \
    } while (0)

#pragma unroll
    for (int c = 0; c < 3; c++) { ISSUE_STAGE(c, c); CP_COMMIT(); }

    for (int c = 0; c < NC; c++) {
        CP_WAIT2();
        __syncthreads();
        if (c + 3 < NC) ISSUE_STAGE((c + 3) & (STAGES - 1), c + 3);
        CP_COMMIT();

        const uint32_t so = (uint32_t)(c & (STAGES - 1)) * STAGE_BYTES;
#pragma unroll
        for (int kk = 0; kk < 2; kk++) {
            uint32_t aF[4][4], bF[4][2];
#pragma unroll
            for (int mi = 0; mi < 4; mi++)
                ldm_x4(aF[mi], aBase + so + kk * 4096 + mi * 256);
#pragma unroll
            for (int ni = 0; ni < 4; ni++)
                ldm_x2(bF[ni], bBase + so + kk * 4096 + ni * 128);
#pragma unroll
            for (int mi = 0; mi < 4; mi++)
#pragma unroll
                for (int ni = 0; ni < 4; ni++)
                    mma_fp8(acc[mi][ni], aF[mi], bF[ni]);
        }
    }

    // ---- fused epilogue: rescale + bias, row (max,sumexp) partials, label gather
    const int tq = lane >> 2, lq = lane & 3;
#pragma unroll
    for (int mi = 0; mi < 4; mi++) {
#pragma unroll
        for (int h = 0; h < 2; h++) {
            const int rloc = wm * 64 + mi * 16 + h * 8 + tq;
            const size_t grow = (size_t)(bm + rloc);
            float v[8];
            float mx = -3.4e38f;
#pragma unroll
            for (int ni = 0; ni < 4; ni++)
#pragma unroll
                for (int e = 0; e < 2; e++) {
                    float f = acc[mi][ni][h * 2 + e] * INV_WSCALE + sbias[wn * 32 + ni * 8 + lq * 2 + e];
                    v[ni * 2 + e] = f;
                    mx = fmaxf(mx, f);
                }
            float sum = 0.f;
#pragma unroll
            for (int i = 0; i < 8; i++) sum += __expf(v[i] - mx);
#pragma unroll
            for (int o = 1; o <= 2; o <<= 1) {
                float mo = __shfl_xor_sync(0xffffffffu, mx, o);
                float so2 = __shfl_xor_sync(0xffffffffu, sum, o);
                float m2 = fmaxf(mx, mo);
                sum = sum * __expf(mx - m2) + so2 * __expf(mo - m2);
                mx = m2;
            }
            if (lq == 0)
                g_part[grow * 128 + blockIdx.x * 4 + wn] = make_float2(mx, sum);
#pragma unroll
            for (int ni = 0; ni < 4; ni++)
#pragma unroll
                for (int e = 0; e < 2; e++) {
                    const int cidx = wn * 32 + ni * 8 + lq * 2 + e;
                    const int slot = stable[cidx];
                    if (slot >= 0) g_gath[grow * Jn + slot] = v[ni * 2 + e];
                }
        }
    }

    // ---- last CTA of this 128-row block does the LSE reduce + emit
    __syncthreads();
    if (tid == 0) {
        __threadfence();
        slast = atomicAdd(&g_rowctr[blockIdx.y], 1);
    }
    __syncthreads();
    if (slast == 31) {
        __threadfence();
        for (int rr = w; rr < 128; rr += 8) {
            const size_t row2 = (size_t)(bm + rr);
            float2 p[4];
#pragma unroll
            for (int i = 0; i < 4; i++) p[i] = g_part[row2 * 128 + lane + 32 * i];
            float m = fmaxf(fmaxf(p[0].x, p[1].x), fmaxf(p[2].x, p[3].x));
#pragma unroll
            for (int o = 16; o > 0; o >>= 1) m = fmaxf(m, __shfl_xor_sync(0xffffffffu, m, o));
            float s = 0.f;
#pragma unroll
            for (int i = 0; i < 4; i++) s += p[i].y * __expf(p[i].x - m);
#pragma unroll
            for (int o = 16; o > 0; o >>= 1) s += __shfl_xor_sync(0xffffffffu, s, o);
            const float lse = m + __logf(s);
#pragma unroll
            for (int j = lane; j < 65; j += 32)
                g_emit[row2 * Jn + j] = (g_gath[row2 * Jn + g_rep[b * Jn + j]] - lse) * LOG2E;
        }
    }
}

// ---------------------------------------------------------------- CTC DP: fused 2-step, halo-4 wavefront
__global__ __launch_bounds__(160) void ctc_dp_kernel(const int* __restrict__ ys,
                                                     const int* __restrict__ hlen,
                                                     const int* __restrict__ ylen,
                                                     float* __restrict__ out) {
    extern __shared__ float sem[];
    __shared__ float sbuf[2][20];
    __shared__ float sal[Smax + 12];

    const int b = blockIdx.x, tid = threadIdx.x;
    const int w = tid >> 5, lane = tid & 31;
    const int s = w * 28 + lane - 4;
    const int inlen = hlen[b];

    {
        const float2* src = (const float2*)(g_emit + (size_t)b * Tn * Jn);
        float2* dst = (float2*)sem;
        const int n2 = inlen * (Jn / 2);
        for (int i = tid; i < n2; i += 160) dst[i] = src[i];
    }

    // lane constants: emission indices of s, s-1, s-2 and skip flags of s, s-1, s-2
    const int* lb = ys + b * Ln;
    auto jidx = [&](int u) -> int {
        return (u >= 1 && (u & 1)) ? (((u - 1) >> 1) + 1) : 0;
    };
    auto skipf = [&](int u) -> bool {
        if (u < 3 || !(u & 1)) return false;
        const int li = (u - 1) >> 1;
        const int la = lb[li];
        return (la != 0) && (la != lb[li - 1]);
    };
    const int jj = jidx(s), jm1 = jidx(s - 1), jm2 = jidx(s - 2);
    const bool sk = skipf(s), sk1 = skipf(s - 1), sk2 = skipf(s - 2);
    const bool sodd = (s >= 0) && (s & 1);
    __syncthreads();

    float a = (s == 0) ? sem[0] : (s == 1) ? sem[1] : NEGF;
    int pb = 0;
    if (lane >= 28) sbuf[0][w * 4 + lane - 28] = a;
    __syncthreads();

    int t = 1;
    for (; t + 1 < inlen; t += 2) {
        if (lane < 4) a = (w > 0) ? sbuf[pb][(w - 1) * 4 + lane] : NEGF;
        const float* E1 = sem + t * Jn;
        const float e10 = E1[jj], e1m1 = E1[jm1], e1m2 = E1[jm2];
        const float e2 = sem[(t + 1) * Jn + jj];
        // transition kernels (off critical chain)
        const float K1 = lse2(e10, e1m1);
        const float K2 = sk ? lse3(e10, e1m1, e1m2) : e1m1;
        const float K3 = sodd ? (sk ? e1m2 : NEGF) : (sk1 ? e1m1 : NEGF);
        const float K4 = (sk && sk2) ? e1m2 : NEGF;
        const float am1 = __shfl_up_sync(0xffffffffu, a, 1);
        const float am2 = __shfl_up_sync(0xffffffffu, a, 2);
        const float am3 = __shfl_up_sync(0xffffffffu, a, 3);
        const float am4 = __shfl_up_sync(0xffffffffu, a, 4);
        const float t0 = a + e10;
        const float t1 = am1 + K1;
        const float t2 = am2 + K2;
        const float t3 = am3 + K3;
        const float t4 = am4 + K4;
        const float m = fmaxf(fmaxf(fmaxf(t0, t1), fmaxf(t2, t3)), t4);
        a = m + lg2(ex2(t0 - m) + ex2(t1 - m) + ex2(t2 - m) + ex2(t3 - m) + ex2(t4 - m)) + e2;
        pb ^= 1;
        if (lane >= 28) sbuf[pb][w * 4 + lane - 28] = a;
        __syncthreads();
    }
    // odd remainder: one single step
    if (t < inlen) {
        if (lane < 4) a = (w > 0) ? sbuf[pb][(w - 1) * 4 + lane] : NEGF;
        const float e = sem[t * Jn + jj];
        const float up1 = __shfl_up_sync(0xffffffffu, a, 1);
        const float up2 = __shfl_up_sync(0xffffffffu, a, 2);
        const float am2v = sk ? up2 : NEGF;
        const float m = fmaxf(fmaxf(a, up1), am2v);
        a = m + lg2(ex2(a - m) + ex2(up1 - m) + ex2(am2v - m)) + e;
    }

    if (lane >= 4 && s < Smax) sal[s] = a;
    __syncthreads();
    if (tid == 0) {
        const int s2 = 2 * ylen[b];
        const float x = sal[s2], y = sal[s2 - 1];
        const float m = fmaxf(x, y), d = fminf(x, y) - m;
        g_ll[b] = -(m + lg2(1.f + ex2(d))) * LN2;
        __threadfence();
        const int done = atomicAdd(&g_ctr, 1);
        if (done == Bn - 1) {
            float acc = 0.f;
#pragma unroll
            for (int i = 0; i < Bn; i++) acc += g_ll[i];
            out[0] = acc / (float)Bn;
        }
    }
}

// ----------------------------------------------------------------
extern "C" void kernel_launch(void* const* d_in, const int* in_sizes, int n_in,
                              void* d_out, int out_size) {
    const float* hs   = (const float*)d_in[0];
    const int*   hlen = (const int*)d_in[1];
    const int*   ys   = (const int*)d_in[2];
    const int*   ylen = (const int*)d_in[3];
    const float* Wm   = (const float*)d_in[4];
    const float* bias = (const float*)d_in[5];
    float* out = (float*)d_out;

    static bool attrs_set = false;
    if (!attrs_set) {
        cudaFuncSetAttribute(gemm_mma_kernel, cudaFuncAttributeMaxDynamicSharedMemorySize, GEMM_SMEM);
        cudaFuncSetAttribute(ctc_dp_kernel, cudaFuncAttributeMaxDynamicSharedMemorySize, Tn * Jn * 4);
        attrs_set = true;
    }

    prep_kernel<<<6161, 256>>>(hs, Wm, ys);
    gemm_mma_kernel<<<dim3(Vn / 128, Mn / 128), 256, GEMM_SMEM>>>(ys, bias);
    ctc_dp_kernel<<<Bn, 160, Tn * Jn * 4>>>(ys, hlen, ylen, out);
}

// round 13
// speedup vs baseline: 1.0859x; 1.0859x over previous
#include <cuda_runtime.h>
#include <cuda_bf16.h>
#include <cuda_fp8.h>
#include <math.h>
#include <stdint.h>

// ---------------------------------------------------------------- shapes
constexpr int Bn = 16, Tn = 512, Hn = 512, Vn = 4096, Ln = 64, Jn = 66;
constexpr int Mn = Bn * Tn;
constexpr int Smax = 2 * Ln + 1;
constexpr float NEGF = -1e30f;
constexpr float LOG2E = 1.4426950408889634f;
constexpr float LN2 = 0.6931471805599453f;
constexpr float WSCALE = 16.0f;
constexpr float INV_WSCALE = 1.0f / 16.0f;

// ---------------------------------------------------------------- scratch
__device__ uint8_t g_A8[(size_t)Mn * Hn];
__device__ uint8_t g_B8[(size_t)Vn * Hn];
__device__ float2  g_part[(size_t)Mn * 128];
__device__ float   g_gath[(size_t)Mn * Jn];
__device__ float   g_emit[(size_t)Mn * Jn];
__device__ int     g_rep[Bn * Jn];
__device__ float   g_ll[Bn];
__device__ int     g_ctr;

// ---------------------------------------------------------------- helpers
__device__ __forceinline__ uint32_t smem_u32(const void* p) {
    uint32_t a;
    asm("{ .reg .u64 t; cvta.to.shared.u64 t, %1; cvt.u32.u64 %0, t; }" : "=r"(a) : "l"(p));
    return a;
}
__device__ __forceinline__ void ldm_x4(uint32_t* r, uint32_t addr) {
    asm volatile("ldmatrix.sync.aligned.m8n8.x4.shared.b16 {%0,%1,%2,%3}, [%4];"
                 : "=r"(r[0]), "=r"(r[1]), "=r"(r[2]), "=r"(r[3]) : "r"(addr));
}
__device__ __forceinline__ void ldm_x2(uint32_t* r, uint32_t addr) {
    asm volatile("ldmatrix.sync.aligned.m8n8.x2.shared.b16 {%0,%1}, [%2];"
                 : "=r"(r[0]), "=r"(r[1]) : "r"(addr));
}
__device__ __forceinline__ void mma_fp8(float* d, const uint32_t* a, const uint32_t* b) {
    asm volatile("mma.sync.aligned.m16n8k32.row.col.f32.e4m3.e4m3.f32 "
                 "{%0,%1,%2,%3}, {%4,%5,%6,%7}, {%8,%9}, {%0,%1,%2,%3};"
                 : "+f"(d[0]), "+f"(d[1]), "+f"(d[2]), "+f"(d[3])
                 : "r"(a[0]), "r"(a[1]), "r"(a[2]), "r"(a[3]), "r"(b[0]), "r"(b[1]));
}
__device__ __forceinline__ float ex2(float x) {
    float r; asm("ex2.approx.ftz.f32 %0, %1;" : "=f"(r) : "f"(x)); return r;
}
__device__ __forceinline__ float lg2(float x) {
    float r; asm("lg2.approx.f32 %0, %1;" : "=f"(r) : "f"(x)); return r;
}
__device__ __forceinline__ float lse2(float x, float y) {
    float m = fmaxf(x, y);
    return m + lg2(ex2(x - m) + ex2(y - m));
}
__device__ __forceinline__ float lse3(float x, float y, float z) {
    float m = fmaxf(fmaxf(x, y), z);
    return m + lg2(ex2(x - m) + ex2(y - m) + ex2(z - m));
}
__device__ __forceinline__ uint16_t f2_to_e4m3x2(float x, float y) {
    return (uint16_t)__nv_cvt_float2_to_fp8x2(make_float2(x, y), __NV_SATFINITE, __NV_E4M3);
}
#define CP_ASYNC16(dst, src) \
    asm volatile("cp.async.cg.shared.global [%0], [%1], 16;" :: "r"(dst), "l"(src) : "memory")
#define CP_COMMIT() asm volatile("cp.async.commit_group;" ::: "memory")
#define CP_WAIT2()  asm volatile("cp.async.wait_group 2;" ::: "memory")

// ---------------------------------------------------------------- fused preprocessing
__global__ __launch_bounds__(256) void prep_kernel(const float* __restrict__ hs,
                                                   const float* __restrict__ W,
                                                   const int* __restrict__ ys) {
    const int bid = blockIdx.x, tid = threadIdx.x;
    if (bid < 4096) {
        size_t i = (size_t)bid * 256 + tid;
        float4 v = ((const float4*)hs)[i];
        uint32_t u = (uint32_t)f2_to_e4m3x2(v.x, v.y) | ((uint32_t)f2_to_e4m3x2(v.z, v.w) << 16);
        ((uint32_t*)g_A8)[i] = u;
    } else if (bid < 6144) {
        __shared__ float tile[32][33];
        const int vb = bid - 4096;
        const int v0 = (vb & 127) * 32, k0 = (vb >> 7) * 32;
        const int tx = tid & 31, ty = tid >> 5;
#pragma unroll
        for (int j = 0; j < 4; j++)
            tile[ty + 8 * j][tx] = W[(size_t)(k0 + ty + 8 * j) * Vn + v0 + tx];
        __syncthreads();
#pragma unroll
        for (int j = 0; j < 4; j++) {
            int vl = ty + 8 * j;
            __nv_fp8_e4m3 q(tile[tx][vl] * WSCALE);
            g_B8[(size_t)(v0 + vl) * Hn + k0 + tx] = *(uint8_t*)&q;
        }
    } else if (bid < 6160) {
        const int b = bid - 6144;
        const int j = tid;
        if (j < 65) {
            const int vid = (j == 0) ? 0 : ys[b * Ln + j - 1];
            int r = j;
            for (int q = 0; q < j; q++) {
                const int vq = (q == 0) ? 0 : ys[b * Ln + q - 1];
                if (vq == vid) { r = q; break; }
            }
            g_rep[b * Jn + j] = r;
        }
    } else {
        if (tid == 0) g_ctr = 0;
    }
}

// ---------------------------------------------------------------- FP8 MMA GEMM (R11 exact)
constexpr int STAGES = 4;
constexpr int STAGE_BYTES = 16384;
constexpr int GEMM_SMEM = STAGES * STAGE_BYTES;

__global__ __launch_bounds__(256, 2) void gemm_mma_kernel(const int* __restrict__ ys,
                                                          const float* __restrict__ bias) {
    extern __shared__ __align__(1024) char sm[];
    __shared__ float sbias[128];
    __shared__ int stable[128];

    const int tid = threadIdx.x, w = tid >> 5, lane = tid & 31;
    const int bn = blockIdx.x * 128, bm = blockIdx.y * 128;
    const int b = blockIdx.y >> 2;

    if (tid < 128) { sbias[tid] = bias[bn + tid]; stable[tid] = -1; }
    __syncthreads();
    if (tid == 0) {
        for (int j = 0; j < 65; j++) {
            const int vid = (j == 0) ? 0 : ys[b * Ln + j - 1];
            const int idx = vid - bn;
            if (idx >= 0 && idx < 128 && stable[idx] < 0) stable[idx] = j;
        }
    }

    const int row = tid >> 1, kp = tid & 1;
    const uint8_t* gA = g_A8 + (size_t)(bm + row) * Hn + kp * 16;
    const uint8_t* gB = g_B8 + (size_t)(bn + row) * Hn + kp * 16;
    const uint32_t smb = smem_u32(sm);
    const uint32_t stsA = smb + (uint32_t)(kp * 2) * 2048 + (uint32_t)row * 16;

    const int wm = w >> 2, wn = w & 3;
    const uint32_t aBase = smb + (uint32_t)(wm * 64 + (lane & 15)) * 16 + (uint32_t)(lane >> 4) * 2048;
    const uint32_t bBase = smb + 8192 + (uint32_t)(wn * 32 + (lane & 7)) * 16 + (uint32_t)((lane >> 3) & 1) * 2048;

    float acc[4][4][4];
#pragma unroll
    for (int mi = 0; mi < 4; mi++)
#pragma unroll
        for (int ni = 0; ni < 4; ni++)
#pragma unroll
            for (int e = 0; e < 4; e++) acc[mi][ni][e] = 0.f;

    const int NC = Hn / 64;

#define ISSUE_STAGE(slot, c)                                                   \
    do {                                                                       \
        const uint32_t so = (uint32_t)(slot) * STAGE_BYTES;                    \
        _Pragma("unroll")                                                      \
        for (int i = 0; i < 2; i++) {                                          \
            CP_ASYNC16(stsA + so + i * 2048, gA + (c) * 64 + i * 32);          \
            CP_ASYNC16(stsA + so + 8192 + i * 2048, gB + (c) * 64 + i * 32);   \
        }                                                                      \
    } while (0)

#pragma unroll
    for (int c = 0; c < 3; c++) { ISSUE_STAGE(c, c); CP_COMMIT(); }

    for (int c = 0; c < NC; c++) {
        CP_WAIT2();
        __syncthreads();
        if (c + 3 < NC) ISSUE_STAGE((c + 3) & (STAGES - 1), c + 3);
        CP_COMMIT();

        const uint32_t so = (uint32_t)(c & (STAGES - 1)) * STAGE_BYTES;
#pragma unroll
        for (int kk = 0; kk < 2; kk++) {
            uint32_t aF[4][4], bF[4][2];
#pragma unroll
            for (int mi = 0; mi < 4; mi++)
                ldm_x4(aF[mi], aBase + so + kk * 4096 + mi * 256);
#pragma unroll
            for (int ni = 0; ni < 4; ni++)
                ldm_x2(bF[ni], bBase + so + kk * 4096 + ni * 128);
#pragma unroll
            for (int mi = 0; mi < 4; mi++)
#pragma unroll
                for (int ni = 0; ni < 4; ni++)
                    mma_fp8(acc[mi][ni], aF[mi], bF[ni]);
        }
    }

    const int tq = lane >> 2, lq = lane & 3;
#pragma unroll
    for (int mi = 0; mi < 4; mi++) {
#pragma unroll
        for (int h = 0; h < 2; h++) {
            const int rloc = wm * 64 + mi * 16 + h * 8 + tq;
            const size_t grow = (size_t)(bm + rloc);
            float v[8];
            float mx = -3.4e38f;
#pragma unroll
            for (int ni = 0; ni < 4; ni++)
#pragma unroll
                for (int e = 0; e < 2; e++) {
                    float f = acc[mi][ni][h * 2 + e] * INV_WSCALE + sbias[wn * 32 + ni * 8 + lq * 2 + e];
                    v[ni * 2 + e] = f;
                    mx = fmaxf(mx, f);
                }
            float sum = 0.f;
#pragma unroll
            for (int i = 0; i < 8; i++) sum += __expf(v[i] - mx);
#pragma unroll
            for (int o = 1; o <= 2; o <<= 1) {
                float mo = __shfl_xor_sync(0xffffffffu, mx, o);
                float so2 = __shfl_xor_sync(0xffffffffu, sum, o);
                float m2 = fmaxf(mx, mo);
                sum = sum * __expf(mx - m2) + so2 * __expf(mo - m2);
                mx = m2;
            }
            if (lq == 0)
                g_part[grow * 128 + blockIdx.x * 4 + wn] = make_float2(mx, sum);
#pragma unroll
            for (int ni = 0; ni < 4; ni++)
#pragma unroll
                for (int e = 0; e < 2; e++) {
                    const int cidx = wn * 32 + ni * 8 + lq * 2 + e;
                    const int slot = stable[cidx];
                    if (slot >= 0) g_gath[grow * Jn + slot] = v[ni * 2 + e];
                }
        }
    }
}

// ---------------------------------------------------------------- LSE reduce (128 partials/row) + emit
__global__ __launch_bounds__(256) void lse_emit_kernel() {
    const int warp = threadIdx.x >> 5, lane = threadIdx.x & 31;
    const size_t row = (size_t)blockIdx.x * 8 + warp;
    const int b = (int)(row >> 9);
    float2 p[4];
#pragma unroll
    for (int i = 0; i < 4; i++) p[i] = g_part[row * 128 + lane + 32 * i];
    float m = fmaxf(fmaxf(p[0].x, p[1].x), fmaxf(p[2].x, p[3].x));
#pragma unroll
    for (int o = 16; o > 0; o >>= 1) m = fmaxf(m, __shfl_xor_sync(0xffffffffu, m, o));
    float s = 0.f;
#pragma unroll
    for (int i = 0; i < 4; i++) s += p[i].y * __expf(p[i].x - m);
#pragma unroll
    for (int o = 16; o > 0; o >>= 1) s += __shfl_xor_sync(0xffffffffu, s, o);
    const float lse = m + __logf(s);
#pragma unroll
    for (int j = lane; j < 65; j += 32)
        g_emit[row * Jn + j] = (g_gath[row * Jn + g_rep[b * Jn + j]] - lse) * LOG2E;
}

// ---------------------------------------------------------------- CTC DP: fused 2-step, halo-4 wavefront
__global__ __launch_bounds__(160) void ctc_dp_kernel(const int* __restrict__ ys,
                                                     const int* __restrict__ hlen,
                                                     const int* __restrict__ ylen,
                                                     float* __restrict__ out) {
    extern __shared__ float sem[];
    __shared__ float sbuf[2][20];
    __shared__ float sal[Smax + 12];

    const int b = blockIdx.x, tid = threadIdx.x;
    const int w = tid >> 5, lane = tid & 31;
    const int s = w * 28 + lane - 4;
    const int inlen = hlen[b];

    {
        const float2* src = (const float2*)(g_emit + (size_t)b * Tn * Jn);
        float2* dst = (float2*)sem;
        const int n2 = inlen * (Jn / 2);
        for (int i = tid; i < n2; i += 160) dst[i] = src[i];
    }

    const int* lb = ys + b * Ln;
    auto jidx = [&](int u) -> int {
        return (u >= 1 && (u & 1)) ? (((u - 1) >> 1) + 1) : 0;
    };
    auto skipf = [&](int u) -> bool {
        if (u < 3 || !(u & 1)) return false;
        const int li = (u - 1) >> 1;
        const int la = lb[li];
        return (la != 0) && (la != lb[li - 1]);
    };
    const int jj = jidx(s), jm1 = jidx(s - 1), jm2 = jidx(s - 2);
    const bool sk = skipf(s), sk1 = skipf(s - 1), sk2 = skipf(s - 2);
    const bool sodd = (s >= 0) && (s & 1);
    __syncthreads();

    float a = (s == 0) ? sem[0] : (s == 1) ? sem[1] : NEGF;
    int pb = 0;
    if (lane >= 28) sbuf[0][w * 4 + lane - 28] = a;
    __syncthreads();

    int t = 1;
    for (; t + 1 < inlen; t += 2) {
        if (lane < 4) a = (w > 0) ? sbuf[pb][(w - 1) * 4 + lane] : NEGF;
        const float* E1 = sem + t * Jn;
        const float e10 = E1[jj], e1m1 = E1[jm1], e1m2 = E1[jm2];
        const float e2 = sem[(t + 1) * Jn + jj];
        const float K1 = lse2(e10, e1m1);
        const float K2 = sk ? lse3(e10, e1m1, e1m2) : e1m1;
        const float K3 = sodd ? (sk ? e1m2 : NEGF) : (sk1 ? e1m1 : NEGF);
        const float K4 = (sk && sk2) ? e1m2 : NEGF;
        const float am1 = __shfl_up_sync(0xffffffffu, a, 1);
        const float am2 = __shfl_up_sync(0xffffffffu, a, 2);
        const float am3 = __shfl_up_sync(0xffffffffu, a, 3);
        const float am4 = __shfl_up_sync(0xffffffffu, a, 4);
        const float t0 = a + e10;
        const float t1 = am1 + K1;
        const float t2 = am2 + K2;
        const float t3 = am3 + K3;
        const float t4 = am4 + K4;
        const float m = fmaxf(fmaxf(fmaxf(t0, t1), fmaxf(t2, t3)), t4);
        a = m + lg2(ex2(t0 - m) + ex2(t1 - m) + ex2(t2 - m) + ex2(t3 - m) + ex2(t4 - m)) + e2;
        pb ^= 1;
        if (lane >= 28) sbuf[pb][w * 4 + lane - 28] = a;
        __syncthreads();
    }
    if (t < inlen) {
        if (lane < 4) a = (w > 0) ? sbuf[pb][(w - 1) * 4 + lane] : NEGF;
        const float e = sem[t * Jn + jj];
        const float up1 = __shfl_up_sync(0xffffffffu, a, 1);
        const float up2 = __shfl_up_sync(0xffffffffu, a, 2);
        const float am2v = sk ? up2 : NEGF;
        const float m = fmaxf(fmaxf(a, up1), am2v);
        a = m + lg2(ex2(a - m) + ex2(up1 - m) + ex2(am2v - m)) + e;
    }

    if (lane >= 4 && s < Smax) sal[s] = a;
    __syncthreads();
    if (tid == 0) {
        const int s2 = 2 * ylen[b];
        const float x = sal[s2], y = sal[s2 - 1];
        const float m = fmaxf(x, y), d = fminf(x, y) - m;
        g_ll[b] = -(m + lg2(1.f + ex2(d))) * LN2;
        __threadfence();
        const int done = atomicAdd(&g_ctr, 1);
        if (done == Bn - 1) {
            float acc = 0.f;
#pragma unroll
            for (int i = 0; i < Bn; i++) acc += g_ll[i];
            out[0] = acc / (float)Bn;
        }
    }
}

// ----------------------------------------------------------------
extern "C" void kernel_launch(void* const* d_in, const int* in_sizes, int n_in,
                              void* d_out, int out_size) {
    const float* hs   = (const float*)d_in[0];
    const int*   hlen = (const int*)d_in[1];
    const int*   ys   = (const int*)d_in[2];
    const int*   ylen = (const int*)d_in[3];
    const float* Wm   = (const float*)d_in[4];
    const float* bias = (const float*)d_in[5];
    float* out = (float*)d_out;

    static bool attrs_set = false;
    if (!attrs_set) {
        cudaFuncSetAttribute(gemm_mma_kernel, cudaFuncAttributeMaxDynamicSharedMemorySize, GEMM_SMEM);
        cudaFuncSetAttribute(ctc_dp_kernel, cudaFuncAttributeMaxDynamicSharedMemorySize, Tn * Jn * 4);
        attrs_set = true;
    }

    prep_kernel<<<6161, 256>>>(hs, Wm, ys);
    gemm_mma_kernel<<<dim3(Vn / 128, Mn / 128), 256, GEMM_SMEM>>>(ys, bias);
    lse_emit_kernel<<<Mn / 8, 256>>>();
    ctc_dp_kernel<<<Bn, 160, Tn * Jn * 4>>>(ys, hlen, ylen, out);
}